// round 16
// baseline (speedup 1.0000x reference)
#include <cuda_runtime.h>
#include <math.h>

#define Nn 50000
#define En 800000
#define Cc 16
#define Mm 32
#define Gg 8
#define CG (Cc*Gg)          // 128
#define NODES_PB 64         // nodes per layer1 block

// ---- scratch (module-static, allowed) ----
__device__ float g_smB1[Cc*Mm*Gg];   // softmax(B1, axis=M)   [c][m][g]
__device__ float g_R[Gg*Mm*Cc];      // R[g][m][i] = sum_l Q[i,l,g]*post0_tab[m][l,g]/norm0
__device__ float g_ll0[Mm*Gg];       // ll0_tab[m][g] = log(norm0(m,g))
__device__ int   g_hist[(size_t)Nn*Mm];  // per-node neighbor symbol histogram
// INVARIANT: g_hist is all-zero at kernel_launch entry (zero-init at load;
// k_layer1 re-zeroes the rows it consumed, so every execution restores it).

// ---------------------------------------------------------------------------
// 1) Fused scatter + table build.
//    Block 0   : softmaxes (no max-shift; inputs bounded +-5) + R/ll0/smB1.
//    Blocks >=1: histogram scatter, 4 edges/thread: hist[src][x[dst]] += 1.
// ---------------------------------------------------------------------------
__global__ void k_scatter(const int* __restrict__ ei, const int* __restrict__ x,
                          const float* __restrict__ B0, const float* __restrict__ Pi,
                          const float* __restrict__ B1, const float* __restrict__ Q)
{
    __shared__ float s_B0[Cc*Mm*Gg];   // 16 KB  [c][m][g]
    __shared__ float s_Q [Cc*Cc*Gg];   //  8 KB  [i][l][g]
    __shared__ float s_Pi[Cc*Gg];      // 512 B  [c][g]

    if (blockIdx.x > 0) {
        int tid = (blockIdx.x - 1) * blockDim.x + threadIdx.x;
        if (tid >= En / 4) return;
        int e0 = tid * 4;

        const int4 S = *reinterpret_cast<const int4*>(ei + e0);        // 4 src
        const int4 D = *reinterpret_cast<const int4*>(ei + En + e0);   // 4 dst

        int x0 = __ldg(x + D.x);
        int x1 = __ldg(x + D.y);
        int x2 = __ldg(x + D.z);
        int x3 = __ldg(x + D.w);

        atomicAdd(&g_hist[(size_t)S.x * Mm + x0], 1);
        atomicAdd(&g_hist[(size_t)S.y * Mm + x1], 1);
        atomicAdd(&g_hist[(size_t)S.z * Mm + x2], 1);
        atomicAdd(&g_hist[(size_t)S.w * Mm + x3], 1);
        return;
    }

    // ---- block 0: table build ----
    int t = threadIdx.x;

    if (t < 128) {
        int g = t & 7, r = t >> 3;
        // B0 row (c=r, g): softmax over m (no max-shift)
        float e[Mm]; float s = 0.f;
        #pragma unroll
        for (int m = 0; m < Mm; m++) { e[m] = expf(B0[r*Mm*Gg + m*Gg + g]); s += e[m]; }
        float inv = 1.f / s;
        #pragma unroll
        for (int m = 0; m < Mm; m++) s_B0[r*Mm*Gg + m*Gg + g] = e[m] * inv;

        // Q column (l=r, g): softmax over i
        float eq[Cc]; float sq = 0.f;
        #pragma unroll
        for (int i = 0; i < Cc; i++) { eq[i] = expf(Q[i*Cc*Gg + r*Gg + g]); sq += eq[i]; }
        float invq = 1.f / sq;
        #pragma unroll
        for (int i = 0; i < Cc; i++) s_Q[i*Cc*Gg + r*Gg + g] = eq[i] * invq;

        // Pi column g (threads 0..7): softmax over c
        if (t < Gg) {
            float ep[Cc]; float sp = 0.f;
            #pragma unroll
            for (int c = 0; c < Cc; c++) { ep[c] = expf(Pi[c*Gg + t]); sp += ep[c]; }
            float invp = 1.f / sp;
            #pragma unroll
            for (int c = 0; c < Cc; c++) s_Pi[c*Gg + t] = ep[c] * invp;
        }
    } else {
        // B1 row: threads 128..255 -> straight to global (consumed by k_layer1).
        int t2 = t - 128;
        int g = t2 & 7, r = t2 >> 3;
        float e[Mm]; float s = 0.f;
        #pragma unroll
        for (int m = 0; m < Mm; m++) { e[m] = expf(B1[r*Mm*Gg + m*Gg + g]); s += e[m]; }
        float inv = 1.f / s;
        #pragma unroll
        for (int m = 0; m < Mm; m++) g_smB1[r*Mm*Gg + m*Gg + g] = e[m] * inv;
    }
    __syncthreads();

    // R + ll0 tables: thread t -> (m = t>>3, g = t&7). 256 threads = 32m x 8g.
    {
        int m = t >> 3, g = t & 7;
        float u[Cc]; float s = 0.f;
        #pragma unroll
        for (int l = 0; l < Cc; l++) {
            u[l] = s_Pi[l*Gg + g] * s_B0[l*Mm*Gg + m*Gg + g];
            s += u[l];
        }
        g_ll0[m*Gg + g] = logf(s);
        float inv = 1.f / s;
        #pragma unroll
        for (int i = 0; i < Cc; i++) {
            float acc = 0.f;
            #pragma unroll
            for (int l = 0; l < Cc; l++)
                acc += s_Q[i*Cc*Gg + l*Gg + g] * u[l];
            g_R[g*Mm*Cc + m*Cc + i] = acc * inv;
        }
    }
}

// ---------------------------------------------------------------------------
// 2) Layer 1. Block = 256 threads / 64 nodes. Thread decode:
//      g = t&7, ih = (t>>3)&1 (which i-half), q = t>>4 (0..15) -> 4 nodes.
//    Accumulators: 4 nodes x 8 i = 32 regs (half of R15) -> 3 blocks/SM.
//    Per m: 2x LDS.128 of R half-row feed 32 FMAs; lanes 16..31 broadcast
//    the same R addresses. Pair (ih flip = lane^8) combines half-norms via
//    one shfl_xor. hist staged as floats; consumed cells re-zeroed (self-
//    cleaning invariant). s_R rows padded 516, s_h rows padded 33.
// ---------------------------------------------------------------------------
__global__ void __launch_bounds__(256, 3)
k_layer1(const int* __restrict__ x, float* __restrict__ out)
{
    __shared__ float s_R[Gg * 516];          // 16.5 KB
    __shared__ float s_h[NODES_PB * 33];     //  8.4 KB
    __shared__ int   s_x[NODES_PB];

    int t   = threadIdx.x;
    int bn0 = blockIdx.x * NODES_PB;

    // cooperative load of R: thread t -> 16 consecutive floats of g-row (t>>5)
    {
        int g   = t >> 5;
        int rem = (t & 31) * 16;
        const float4* src = reinterpret_cast<const float4*>(g_R + g * (Mm*Cc) + rem);
        float4*       dst = reinterpret_cast<float4*>(s_R + g * 516 + rem);
        dst[0] = src[0]; dst[1] = src[1]; dst[2] = src[2]; dst[3] = src[3];
    }
    // cooperative load of hist (int -> float) + re-zero of consumed cells.
    // thread t -> row t>>2 (0..63), 8 ints at col (t&3)*8.
    {
        int row = t >> 2;
        int cb  = (t & 3) * 8;
        float* dp = s_h + row * 33 + cb;
        if (bn0 + row < Nn) {
            int4* src = reinterpret_cast<int4*>(
                g_hist + (size_t)(bn0 + row) * Mm + cb);
            int4 v0 = src[0], v1 = src[1];
            dp[0] = (float)v0.x; dp[1] = (float)v0.y;
            dp[2] = (float)v0.z; dp[3] = (float)v0.w;
            dp[4] = (float)v1.x; dp[5] = (float)v1.y;
            dp[6] = (float)v1.z; dp[7] = (float)v1.w;
            const int4 z4 = make_int4(0, 0, 0, 0);
            src[0] = z4; src[1] = z4;
        } else {
            #pragma unroll
            for (int k = 0; k < 8; k++) dp[k] = 0.f;
        }
    }
    if (t < NODES_PB) s_x[t] = (bn0 + t < Nn) ? x[bn0 + t] : 0;
    __syncthreads();

    int g  = t & 7;
    int ih = (t >> 3) & 1;              // i-half: i = ih*8 + il
    int q  = t >> 4;                    // 0..15 -> nodes q*4 .. q*4+3
    int nb = q * 4;

    float tv[4][8];
    #pragma unroll
    for (int j = 0; j < 4; j++)
        #pragma unroll
        for (int i = 0; i < 8; i++) tv[j][i] = 0.f;
    float cnt[4] = {0.f, 0.f, 0.f, 0.f};

    const float* Rg = s_R + g * 516 + ih * 8;
    const float* h0 = s_h + (nb + 0) * 33;
    const float* h1 = s_h + (nb + 1) * 33;
    const float* h2 = s_h + (nb + 2) * 33;
    const float* h3 = s_h + (nb + 3) * 33;

    #pragma unroll 4
    for (int m = 0; m < Mm; m++) {
        float4 ra = *reinterpret_cast<const float4*>(Rg + m * Cc);
        float4 rb = *reinterpret_cast<const float4*>(Rg + m * Cc + 4);
        float a0 = h0[m], a1 = h1[m], a2 = h2[m], a3 = h3[m];
        cnt[0] += a0; cnt[1] += a1; cnt[2] += a2; cnt[3] += a3;

        tv[0][0] += a0*ra.x; tv[0][1] += a0*ra.y; tv[0][2] += a0*ra.z; tv[0][3] += a0*ra.w;
        tv[0][4] += a0*rb.x; tv[0][5] += a0*rb.y; tv[0][6] += a0*rb.z; tv[0][7] += a0*rb.w;

        tv[1][0] += a1*ra.x; tv[1][1] += a1*ra.y; tv[1][2] += a1*ra.z; tv[1][3] += a1*ra.w;
        tv[1][4] += a1*rb.x; tv[1][5] += a1*rb.y; tv[1][6] += a1*rb.z; tv[1][7] += a1*rb.w;

        tv[2][0] += a2*ra.x; tv[2][1] += a2*ra.y; tv[2][2] += a2*ra.z; tv[2][3] += a2*ra.w;
        tv[2][4] += a2*rb.x; tv[2][5] += a2*rb.y; tv[2][6] += a2*rb.z; tv[2][7] += a2*rb.w;

        tv[3][0] += a3*ra.x; tv[3][1] += a3*ra.y; tv[3][2] += a3*ra.z; tv[3][3] += a3*ra.w;
        tv[3][4] += a3*rb.x; tv[3][5] += a3*rb.y; tv[3][6] += a3*rb.z; tv[3][7] += a3*rb.w;
    }

    float* p1 = out + (size_t)Nn * 2 * Gg;

    // Epilogue kept warp-uniform: all threads run all 4 iterations and the
    // shfl; only the stores are guarded. Partner lane = lane^8 (same q, g,
    // flipped ih) holds the other i-half of the same node.
    #pragma unroll
    for (int j = 0; j < 4; j++) {
        int n  = bn0 + nb + j;
        int xm = s_x[nb + j];
        float inv_cnt = 1.f / fmaxf(cnt[j], 1.f);

        float w[8]; float nh = 0.f;
        #pragma unroll
        for (int il = 0; il < 8; il++) {
            int i = ih * 8 + il;
            float wv = g_smB1[i*Mm*Gg + xm*Gg + g] * tv[j][il] * inv_cnt;
            w[il] = wv;
            nh += wv;
        }
        float norm = nh + __shfl_xor_sync(0xffffffffu, nh, 8);

        if (n < Nn) {
            if (ih == 0) {
                out[(size_t)n * (2*Gg) + g]      = g_ll0[xm*Gg + g];
                out[(size_t)n * (2*Gg) + Gg + g] = logf(norm);
            }
            float invn = 1.f / norm;
            size_t pbase = (size_t)n * CG + g;
            #pragma unroll
            for (int il = 0; il < 8; il++)
                p1[pbase + (ih*8 + il) * Gg] = w[il] * invn;
        }
    }
}

// ---------------------------------------------------------------------------
extern "C" void kernel_launch(void* const* d_in, const int* in_sizes, int n_in,
                              void* d_out, int out_size)
{
    const int*   x  = (const int*)  d_in[0];
    const int*   ei = (const int*)  d_in[1];   // [2, E]
    const float* B0 = (const float*)d_in[2];
    const float* Pi = (const float*)d_in[3];
    const float* B1 = (const float*)d_in[4];
    const float* Q  = (const float*)d_in[5];
    float* out = (float*)d_out;

    // block 0: table build; blocks 1..782: edge scatter (4 edges/thread)
    k_scatter<<<1 + (En / 4 + 255) / 256, 256>>>(ei, x, B0, Pi, B1, Q);
    k_layer1<<<(Nn + NODES_PB - 1) / NODES_PB, 256>>>(x, out);
}

// round 17
// speedup vs baseline: 1.0364x; 1.0364x over previous
#include <cuda_runtime.h>
#include <math.h>

#define Nn 50000
#define En 800000
#define Cc 16
#define Mm 32
#define Gg 8
#define CG (Cc*Gg)          // 128
#define NODES_PB 128        // nodes per layer1 block

// ---- scratch (module-static, allowed) ----
__device__ float g_B1t[Mm*Gg*Cc];    // B1t[m][g][i] = softmax(B1,axis=m)[i,m,g]
__device__ float g_R[Gg*Mm*Cc];      // R[g][m][i] = sum_l Q[i,l,g]*post0_tab[m][l,g]/norm0
__device__ float g_ll0[Mm*Gg];       // ll0_tab[m][g] = log(norm0(m,g))
__device__ int   g_hist[(size_t)Nn*Mm];  // per-node neighbor symbol histogram
// INVARIANT: g_hist is all-zero at kernel_launch entry (zero-init at load;
// k_layer1 re-zeroes the rows it consumed, so every execution restores it).

// packed fp32x2 (sm_100+). FFMA2: d = a*b + d, per 32-bit lane, IEEE fma.
#define FFMA2(d,a,b) asm("fma.rn.f32x2 %0, %1, %2, %0;" : "+l"(d) : "l"(a), "l"(b))
#define ADD2(d,a)    asm("add.rn.f32x2 %0, %0, %1;"     : "+l"(d) : "l"(a))
#define UNPK2(lo,hi,v) asm("mov.b64 {%0, %1}, %2;" : "=f"(lo), "=f"(hi) : "l"(v))

// ---------------------------------------------------------------------------
// 1) Fused scatter + table build.
//    Block 0   : softmaxes (no max-shift; inputs bounded +-5) + R/ll0/B1t.
//    Blocks >=1: histogram scatter, 4 edges/thread: hist[src][x[dst]] += 1.
// ---------------------------------------------------------------------------
__global__ void k_scatter(const int* __restrict__ ei, const int* __restrict__ x,
                          const float* __restrict__ B0, const float* __restrict__ Pi,
                          const float* __restrict__ B1, const float* __restrict__ Q)
{
    __shared__ float s_B0[Cc*Mm*Gg];   // 16 KB  [c][m][g]
    __shared__ float s_Q [Cc*Cc*Gg];   //  8 KB  [i][l][g]
    __shared__ float s_Pi[Cc*Gg];      // 512 B  [c][g]

    if (blockIdx.x > 0) {
        int tid = (blockIdx.x - 1) * blockDim.x + threadIdx.x;
        if (tid >= En / 4) return;
        int e0 = tid * 4;

        const int4 S = *reinterpret_cast<const int4*>(ei + e0);        // 4 src
        const int4 D = *reinterpret_cast<const int4*>(ei + En + e0);   // 4 dst

        int x0 = __ldg(x + D.x);
        int x1 = __ldg(x + D.y);
        int x2 = __ldg(x + D.z);
        int x3 = __ldg(x + D.w);

        atomicAdd(&g_hist[(size_t)S.x * Mm + x0], 1);
        atomicAdd(&g_hist[(size_t)S.y * Mm + x1], 1);
        atomicAdd(&g_hist[(size_t)S.z * Mm + x2], 1);
        atomicAdd(&g_hist[(size_t)S.w * Mm + x3], 1);
        return;
    }

    // ---- block 0: table build ----
    int t = threadIdx.x;

    if (t < 128) {
        int g = t & 7, r = t >> 3;
        // B0 row (c=r, g): softmax over m (no max-shift)
        float e[Mm]; float s = 0.f;
        #pragma unroll
        for (int m = 0; m < Mm; m++) { e[m] = expf(B0[r*Mm*Gg + m*Gg + g]); s += e[m]; }
        float inv = 1.f / s;
        #pragma unroll
        for (int m = 0; m < Mm; m++) s_B0[r*Mm*Gg + m*Gg + g] = e[m] * inv;

        // Q column (l=r, g): softmax over i
        float eq[Cc]; float sq = 0.f;
        #pragma unroll
        for (int i = 0; i < Cc; i++) { eq[i] = expf(Q[i*Cc*Gg + r*Gg + g]); sq += eq[i]; }
        float invq = 1.f / sq;
        #pragma unroll
        for (int i = 0; i < Cc; i++) s_Q[i*Cc*Gg + r*Gg + g] = eq[i] * invq;

        // Pi column g (threads 0..7): softmax over c
        if (t < Gg) {
            float ep[Cc]; float sp = 0.f;
            #pragma unroll
            for (int c = 0; c < Cc; c++) { ep[c] = expf(Pi[c*Gg + t]); sp += ep[c]; }
            float invp = 1.f / sp;
            #pragma unroll
            for (int c = 0; c < Cc; c++) s_Pi[c*Gg + t] = ep[c] * invp;
        }
    } else {
        // B1 row: threads 128..255 -> (c=r, g); write TRANSPOSED to g_B1t
        // so layer1's epilogue reads i-contiguous float4s.
        int t2 = t - 128;
        int g = t2 & 7, r = t2 >> 3;     // r = c = i
        float e[Mm]; float s = 0.f;
        #pragma unroll
        for (int m = 0; m < Mm; m++) { e[m] = expf(B1[r*Mm*Gg + m*Gg + g]); s += e[m]; }
        float inv = 1.f / s;
        #pragma unroll
        for (int m = 0; m < Mm; m++) g_B1t[(m*Gg + g)*Cc + r] = e[m] * inv;
    }
    __syncthreads();

    // R + ll0 tables: thread t -> (m = t>>3, g = t&7). 256 threads = 32m x 8g.
    {
        int m = t >> 3, g = t & 7;
        float u[Cc]; float s = 0.f;
        #pragma unroll
        for (int l = 0; l < Cc; l++) {
            u[l] = s_Pi[l*Gg + g] * s_B0[l*Mm*Gg + m*Gg + g];
            s += u[l];
        }
        g_ll0[m*Gg + g] = logf(s);
        float inv = 1.f / s;
        #pragma unroll
        for (int i = 0; i < Cc; i++) {
            float acc = 0.f;
            #pragma unroll
            for (int l = 0; l < Cc; l++)
                acc += s_Q[i*Cc*Gg + l*Gg + g] * u[l];
            g_R[g*Mm*Cc + m*Cc + i] = acc * inv;
        }
    }
}

// ---------------------------------------------------------------------------
// 2) Layer 1. Block = 256 threads / 128 nodes; thread (q = t>>3, g = t&7)
//    processes 4 nodes x 16 i, accumulating in PACKED f32x2 (tv2[4][8] u64).
//    hist staged in smem as DUPLICATED float2 {h,h} -> the loop feeds FFMA2
//    with one LDS.64 per node per m, zero pack instructions.
//    Per m: 4 LDS.128 (R pairs) + 4 LDS.64 + 4 add.f32x2 + 32 FFMA2.
//    Consumed g_hist cells re-zeroed (self-cleaning). s_R rows padded 516
//    (conflict-free), s_h2 rows padded 33 u64.
// ---------------------------------------------------------------------------
__global__ void __launch_bounds__(256, 2)
k_layer1(const int* __restrict__ x, float* __restrict__ out)
{
    __shared__ float s_R[Gg * 516];                    // 16.5 KB
    __shared__ unsigned long long s_h2[NODES_PB * 33]; // 33.8 KB
    __shared__ int   s_x[NODES_PB];

    int t   = threadIdx.x;
    int bn0 = blockIdx.x * NODES_PB;

    // cooperative load of R: thread t -> 16 consecutive floats of g-row (t>>5)
    {
        int g   = t >> 5;
        int rem = (t & 31) * 16;
        const float4* src = reinterpret_cast<const float4*>(g_R + g * (Mm*Cc) + rem);
        float4*       dst = reinterpret_cast<float4*>(s_R + g * 516 + rem);
        dst[0] = src[0]; dst[1] = src[1]; dst[2] = src[2]; dst[3] = src[3];
    }
    // cooperative hist stage: int -> duplicated float2, + re-zero consumed
    // cells (block-private rows; reader == writer per cell, race-free).
    {
        int row = t >> 1;
        int cb  = (t & 1) * 16;
        if (bn0 + row < Nn) {
            int4* src = reinterpret_cast<int4*>(
                g_hist + (size_t)(bn0 + row) * Mm + cb);
            float2* dp = reinterpret_cast<float2*>(s_h2 + row * 33 + cb);
            const int4 z4 = make_int4(0, 0, 0, 0);
            #pragma unroll
            for (int qq = 0; qq < 4; qq++) {
                int4 v = src[qq];
                dp[qq*4+0] = make_float2((float)v.x, (float)v.x);
                dp[qq*4+1] = make_float2((float)v.y, (float)v.y);
                dp[qq*4+2] = make_float2((float)v.z, (float)v.z);
                dp[qq*4+3] = make_float2((float)v.w, (float)v.w);
                src[qq] = z4;
            }
        }
    }
    if (t < NODES_PB) s_x[t] = (bn0 + t < Nn) ? x[bn0 + t] : 0;
    __syncthreads();

    int q = t >> 3, g = t & 7;          // q: 0..31 -> nodes q*4 .. q*4+3
    int nb = q * 4;

    unsigned long long tv2[4][8];
    #pragma unroll
    for (int j = 0; j < 4; j++)
        #pragma unroll
        for (int k = 0; k < 8; k++) tv2[j][k] = 0ULL;
    unsigned long long cnt2[4] = {0ULL, 0ULL, 0ULL, 0ULL};

    const float* Rg = s_R + g * 516;
    const unsigned long long* h0 = s_h2 + (size_t)(nb + 0) * 33;
    const unsigned long long* h1 = s_h2 + (size_t)(nb + 1) * 33;
    const unsigned long long* h2 = s_h2 + (size_t)(nb + 2) * 33;
    const unsigned long long* h3 = s_h2 + (size_t)(nb + 3) * 33;

    #pragma unroll 4
    for (int m = 0; m < Mm; m++) {
        unsigned long long a0 = h0[m], a1 = h1[m], a2 = h2[m], a3 = h3[m];
        ADD2(cnt2[0], a0); ADD2(cnt2[1], a1);
        ADD2(cnt2[2], a2); ADD2(cnt2[3], a3);

        const ulonglong2* r2 = reinterpret_cast<const ulonglong2*>(Rg + m * Cc);
        ulonglong2 Ra = r2[0], Rb = r2[1], Rc = r2[2], Rd = r2[3];

        FFMA2(tv2[0][0], a0, Ra.x); FFMA2(tv2[0][1], a0, Ra.y);
        FFMA2(tv2[0][2], a0, Rb.x); FFMA2(tv2[0][3], a0, Rb.y);
        FFMA2(tv2[0][4], a0, Rc.x); FFMA2(tv2[0][5], a0, Rc.y);
        FFMA2(tv2[0][6], a0, Rd.x); FFMA2(tv2[0][7], a0, Rd.y);

        FFMA2(tv2[1][0], a1, Ra.x); FFMA2(tv2[1][1], a1, Ra.y);
        FFMA2(tv2[1][2], a1, Rb.x); FFMA2(tv2[1][3], a1, Rb.y);
        FFMA2(tv2[1][4], a1, Rc.x); FFMA2(tv2[1][5], a1, Rc.y);
        FFMA2(tv2[1][6], a1, Rd.x); FFMA2(tv2[1][7], a1, Rd.y);

        FFMA2(tv2[2][0], a2, Ra.x); FFMA2(tv2[2][1], a2, Ra.y);
        FFMA2(tv2[2][2], a2, Rb.x); FFMA2(tv2[2][3], a2, Rb.y);
        FFMA2(tv2[2][4], a2, Rc.x); FFMA2(tv2[2][5], a2, Rc.y);
        FFMA2(tv2[2][6], a2, Rd.x); FFMA2(tv2[2][7], a2, Rd.y);

        FFMA2(tv2[3][0], a3, Ra.x); FFMA2(tv2[3][1], a3, Ra.y);
        FFMA2(tv2[3][2], a3, Rb.x); FFMA2(tv2[3][3], a3, Rb.y);
        FFMA2(tv2[3][4], a3, Rc.x); FFMA2(tv2[3][5], a3, Rc.y);
        FFMA2(tv2[3][6], a3, Rd.x); FFMA2(tv2[3][7], a3, Rd.y);
    }

    float* p1 = out + (size_t)Nn * 2 * Gg;

    #pragma unroll
    for (int j = 0; j < 4; j++) {
        int n = bn0 + nb + j;
        if (n >= Nn) break;
        int xm = s_x[nb + j];

        float tv[Cc];
        #pragma unroll
        for (int k = 0; k < 8; k++) UNPK2(tv[2*k], tv[2*k+1], tv2[j][k]);
        float cj, cdum; UNPK2(cj, cdum, cnt2[j]);
        float inv_cnt = 1.f / fmaxf(cj, 1.f);

        const float4* b4 = reinterpret_cast<const float4*>(
            g_B1t + (xm*Gg + g) * Cc);
        float4 b0 = b4[0], b1 = b4[1], b2 = b4[2], b3 = b4[3];
        float bb[Cc] = {b0.x,b0.y,b0.z,b0.w, b1.x,b1.y,b1.z,b1.w,
                        b2.x,b2.y,b2.z,b2.w, b3.x,b3.y,b3.z,b3.w};

        float v[Cc]; float norm = 0.f;
        #pragma unroll
        for (int i = 0; i < Cc; i++) {
            float w = bb[i] * tv[i] * inv_cnt;
            v[i] = w;
            norm += w;
        }
        out[(size_t)n * (2*Gg) + g]      = g_ll0[xm*Gg + g];
        out[(size_t)n * (2*Gg) + Gg + g] = logf(norm);
        float invn = 1.f / norm;
        size_t pbase = (size_t)n * CG + g;
        #pragma unroll
        for (int i = 0; i < Cc; i++) p1[pbase + i*Gg] = v[i] * invn;
    }
}

// ---------------------------------------------------------------------------
extern "C" void kernel_launch(void* const* d_in, const int* in_sizes, int n_in,
                              void* d_out, int out_size)
{
    const int*   x  = (const int*)  d_in[0];
    const int*   ei = (const int*)  d_in[1];   // [2, E]
    const float* B0 = (const float*)d_in[2];
    const float* Pi = (const float*)d_in[3];
    const float* B1 = (const float*)d_in[4];
    const float* Q  = (const float*)d_in[5];
    float* out = (float*)d_out;

    // block 0: table build; blocks 1..782: edge scatter (4 edges/thread)
    k_scatter<<<1 + (En / 4 + 255) / 256, 256>>>(ei, x, B0, Pi, B1, Q);
    k_layer1<<<(Nn + NODES_PB - 1) / NODES_PB, 256>>>(x, out);
}